// round 1
// baseline (speedup 1.0000x reference)
#include <cuda_runtime.h>
#include <math.h>

#define N_TOK 8192
#define D_DIM 512
#define F_DIM 2048
#define E_NUM 8
#define ASSIGN (2 * N_TOK)

#define BM 64
#define BN 64
#define BK 32

#define EPS_F 2.2204460492503131e-16f

// ---- scratch (allocation-free: __device__ globals) ----
__device__ float g_h[(size_t)ASSIGN * F_DIM];      // 128 MB: relu(h) per assignment
__device__ float g_acc[(size_t)N_TOK * D_DIM];     // 16 MB: combine accumulator
__device__ int   g_e0[N_TOK];
__device__ int   g_e1[N_TOK];
__device__ float g_g0[N_TOK];
__device__ float g_g1[N_TOK];
__device__ int   g_cnt[E_NUM];
__device__ int   g_off[E_NUM];
__device__ int   g_cur[E_NUM];
__device__ int   g_tok[ASSIGN];
__device__ float g_gate[ASSIGN];

// ---- init: zero accumulator + counters ----
__global__ void k_init() {
    size_t i = (size_t)blockIdx.x * blockDim.x + threadIdx.x;
    if (i < (size_t)N_TOK * D_DIM) g_acc[i] = 0.f;
    if (i < E_NUM) { g_cnt[i] = 0; g_cur[i] = 0; }
}

// ---- gating: one warp per token ----
__global__ void k_gate(const float* __restrict__ x, const float* __restrict__ Wg) {
    int gt   = blockIdx.x * blockDim.x + threadIdx.x;
    int warp = gt >> 5;
    int lane = gt & 31;
    if (warp >= N_TOK) return;
    const float* xr = x + (size_t)warp * D_DIM;
    float acc[E_NUM];
#pragma unroll
    for (int e = 0; e < E_NUM; e++) acc[e] = 0.f;
    for (int d = lane; d < D_DIM; d += 32) {
        float xv = xr[d];
        const float* wr = Wg + (size_t)d * E_NUM;
#pragma unroll
        for (int e = 0; e < E_NUM; e++) acc[e] += xv * wr[e];
    }
#pragma unroll
    for (int e = 0; e < E_NUM; e++) {
#pragma unroll
        for (int off = 16; off > 0; off >>= 1)
            acc[e] += __shfl_down_sync(0xffffffffu, acc[e], off);
    }
    if (lane == 0) {
        int e0 = 0; float v0 = acc[0];
#pragma unroll
        for (int e = 1; e < E_NUM; e++)
            if (acc[e] > v0) { v0 = acc[e]; e0 = e; }
        int e1 = -1; float v1 = -INFINITY;
#pragma unroll
        for (int e = 0; e < E_NUM; e++)
            if (e != e0 && acc[e] > v1) { v1 = acc[e]; e1 = e; }
        float t  = expf(v1 - v0);        // v1 <= v0, stable
        float g0 = 1.f / (1.f + t);
        float g1 = t * g0;
        g_e0[warp] = e0; g_e1[warp] = e1;
        g_g0[warp] = g0; g_g1[warp] = g1;
        atomicAdd(&g_cnt[e0], 1);
        atomicAdd(&g_cnt[e1], 1);
    }
}

// ---- exclusive prefix over 8 counts ----
__global__ void k_off() {
    if (threadIdx.x == 0) {
        int s = 0;
        for (int e = 0; e < E_NUM; e++) { g_off[e] = s; s += g_cnt[e]; }
    }
}

// ---- scatter tokens into per-expert buckets ----
__global__ void k_scatter() {
    int n = blockIdx.x * blockDim.x + threadIdx.x;
    if (n >= N_TOK) return;
    int e0 = g_e0[n], e1 = g_e1[n];
    int s0 = atomicAdd(&g_cur[e0], 1);
    int s1 = atomicAdd(&g_cur[e1], 1);
    int p0 = g_off[e0] + s0;
    int p1 = g_off[e1] + s1;
    g_tok[p0] = n; g_gate[p0] = g_g0[n];
    g_tok[p1] = n; g_gate[p1] = g_g1[n];
}

// ---- GEMM1: h = relu(X[bucket] @ W1[e] + b1[e])  [cnt, D] x [D, F] ----
__global__ void k_gemm1(const float* __restrict__ x, const float* __restrict__ W1,
                        const float* __restrict__ b1) {
    int e = blockIdx.z;
    int cnt = g_cnt[e];
    int row0 = blockIdx.x * BM;
    if (row0 >= cnt) return;
    int base = g_off[e];
    int f0 = blockIdx.y * BN;

    __shared__ float As[BK][BM + 4];   // stride 68 floats (16B aligned)
    __shared__ float Bs[BK][BN];
    __shared__ int   toks[BM];

    int tx = threadIdx.x, ty = threadIdx.y;
    int tid = ty * 16 + tx;
    if (tid < BM) {
        int r = row0 + tid;
        toks[tid] = (r < cnt) ? g_tok[base + r] : -1;
    }
    __syncthreads();

    float c[4][4] = {};
    const float* Wb = W1 + (size_t)e * D_DIM * F_DIM;

    for (int k0 = 0; k0 < D_DIM; k0 += BK) {
        // load As (gathered x rows), k contiguous per row
#pragma unroll
        for (int it = 0; it < (BM * BK) / 256; it++) {
            int i = tid + it * 256;
            int m = i >> 5, k = i & 31;
            int t = toks[m];
            As[k][m] = (t >= 0) ? x[(size_t)t * D_DIM + k0 + k] : 0.f;
        }
        // load Bs, f contiguous
#pragma unroll
        for (int it = 0; it < (BK * BN) / 256; it++) {
            int i = tid + it * 256;
            int k = i >> 6, f = i & 63;
            Bs[k][f] = Wb[(size_t)(k0 + k) * F_DIM + f0 + f];
        }
        __syncthreads();
#pragma unroll
        for (int k = 0; k < BK; k++) {
            float4 a = *(const float4*)&As[k][ty * 4];
            float4 b = *(const float4*)&Bs[k][tx * 4];
            c[0][0] += a.x * b.x; c[0][1] += a.x * b.y; c[0][2] += a.x * b.z; c[0][3] += a.x * b.w;
            c[1][0] += a.y * b.x; c[1][1] += a.y * b.y; c[1][2] += a.y * b.z; c[1][3] += a.y * b.w;
            c[2][0] += a.z * b.x; c[2][1] += a.z * b.y; c[2][2] += a.z * b.z; c[2][3] += a.z * b.w;
            c[3][0] += a.w * b.x; c[3][1] += a.w * b.y; c[3][2] += a.w * b.z; c[3][3] += a.w * b.w;
        }
        __syncthreads();
    }

#pragma unroll
    for (int i = 0; i < 4; i++) {
        int r = row0 + ty * 4 + i;
        if (r < cnt) {
#pragma unroll
            for (int j = 0; j < 4; j++) {
                int f = f0 + tx * 4 + j;
                float v = c[i][j] + b1[e * F_DIM + f];
                g_h[(size_t)(base + r) * F_DIM + f] = fmaxf(v, 0.f);
            }
        }
    }
}

// ---- GEMM2: o = h @ W2[e] + b2[e]; acc[token] += gate * exp(o) ----
__global__ void k_gemm2(const float* __restrict__ W2, const float* __restrict__ b2) {
    int e = blockIdx.z;
    int cnt = g_cnt[e];
    int row0 = blockIdx.x * BM;
    if (row0 >= cnt) return;
    int base = g_off[e];
    int d0 = blockIdx.y * BN;

    __shared__ float As[BK][BM + 4];
    __shared__ float Bs[BK][BN];
    __shared__ int   toks[BM];
    __shared__ float gts[BM];

    int tx = threadIdx.x, ty = threadIdx.y;
    int tid = ty * 16 + tx;
    if (tid < BM) {
        int r = row0 + tid;
        toks[tid] = (r < cnt) ? g_tok[base + r] : -1;
        gts[tid]  = (r < cnt) ? g_gate[base + r] : 0.f;
    }
    __syncthreads();

    float c[4][4] = {};
    const float* Wb = W2 + (size_t)e * F_DIM * D_DIM;

    for (int k0 = 0; k0 < F_DIM; k0 += BK) {
        // load As from g_h (rows contiguous in bucket order)
#pragma unroll
        for (int it = 0; it < (BM * BK) / 256; it++) {
            int i = tid + it * 256;
            int m = i >> 5, k = i & 31;
            int r = row0 + m;
            As[k][m] = (r < cnt) ? g_h[(size_t)(base + r) * F_DIM + k0 + k] : 0.f;
        }
#pragma unroll
        for (int it = 0; it < (BK * BN) / 256; it++) {
            int i = tid + it * 256;
            int k = i >> 6, d = i & 63;
            Bs[k][d] = Wb[(size_t)(k0 + k) * D_DIM + d0 + d];
        }
        __syncthreads();
#pragma unroll
        for (int k = 0; k < BK; k++) {
            float4 a = *(const float4*)&As[k][ty * 4];
            float4 b = *(const float4*)&Bs[k][tx * 4];
            c[0][0] += a.x * b.x; c[0][1] += a.x * b.y; c[0][2] += a.x * b.z; c[0][3] += a.x * b.w;
            c[1][0] += a.y * b.x; c[1][1] += a.y * b.y; c[1][2] += a.y * b.z; c[1][3] += a.y * b.w;
            c[2][0] += a.z * b.x; c[2][1] += a.z * b.y; c[2][2] += a.z * b.z; c[2][3] += a.z * b.w;
            c[3][0] += a.w * b.x; c[3][1] += a.w * b.y; c[3][2] += a.w * b.z; c[3][3] += a.w * b.w;
        }
        __syncthreads();
    }

#pragma unroll
    for (int i = 0; i < 4; i++) {
        int r = row0 + ty * 4 + i;
        if (r < cnt) {
            int tok = toks[ty * 4 + i];
            float g = gts[ty * 4 + i];
#pragma unroll
            for (int j = 0; j < 4; j++) {
                int d = d0 + tx * 4 + j;
                float o = c[i][j] + b2[e * D_DIM + d];
                atomicAdd(&g_acc[(size_t)tok * D_DIM + d], g * expf(o));
            }
        }
    }
}

// ---- finalize: log with eps floor ----
__global__ void k_fin(float* __restrict__ out) {
    size_t i = (size_t)blockIdx.x * blockDim.x + threadIdx.x;
    if (i < (size_t)N_TOK * D_DIM) {
        float a = g_acc[i];
        out[i] = logf(a == 0.f ? EPS_F : a);
    }
}

extern "C" void kernel_launch(void* const* d_in, const int* in_sizes, int n_in,
                              void* d_out, int out_size) {
    const float* x  = (const float*)d_in[0];
    const float* Wg = (const float*)d_in[1];
    const float* W1 = (const float*)d_in[2];
    const float* b1 = (const float*)d_in[3];
    const float* W2 = (const float*)d_in[4];
    const float* b2 = (const float*)d_in[5];
    float* out = (float*)d_out;

    int nElem = N_TOK * D_DIM;

    k_init<<<(nElem + 255) / 256, 256>>>();
    k_gate<<<(N_TOK * 32 + 255) / 256, 256>>>(x, Wg);
    k_off<<<1, 32>>>();
    k_scatter<<<(N_TOK + 255) / 256, 256>>>();

    dim3 blk(16, 16);
    k_gemm1<<<dim3(N_TOK / BM, F_DIM / BN, E_NUM), blk>>>(x, W1, b1);
    k_gemm2<<<dim3(N_TOK / BM, D_DIM / BN, E_NUM), blk>>>(W2, b2);

    k_fin<<<(nElem + 255) / 256, 256>>>(out);
}